// round 2
// baseline (speedup 1.0000x reference)
#include <cuda_runtime.h>

#define EPSV 1e-7f
typedef unsigned long long u64;

// ---------------- scratch: single aliased pool (no allocs) ----------------
#define N_MAX 131072
// layout (floats):
//   stage 1:  b1 = pool+0        [N*384]
//             b2 = pool+N*384    [N*384]
//             dt1= pool+N*768    [N*128]
//   stage 2 (stage-1 buffers dead by then):
//             c1 = pool+0        [N*768]
//             c2 = pool+N*768    [N*768]
//             dt2= pool+N*1536   [N*256]
__device__ __align__(256) float g_pool[(size_t)N_MAX*1792];
__device__ __align__(256) float g_pool1[32*128*3];
__device__ __align__(256) float g_r3[32*128*3];
__device__ __align__(256) float g_pool2[32*256*3];
__device__ __align__(256) float g_bf[32*256*3];
__device__ __align__(256) float g_bd[32*256*3];

// ---------------- f32x2 packed helpers (Blackwell packed fp32) ----------------
__device__ __forceinline__ u64 pack2(float lo, float hi){
    u64 r; asm("mov.b64 %0, {%1, %2};" : "=l"(r) : "f"(lo), "f"(hi)); return r;
}
__device__ __forceinline__ void unpack2(u64 v, float& lo, float& hi){
    asm("mov.b64 {%0, %1}, %2;" : "=f"(lo), "=f"(hi) : "l"(v));
}
__device__ __forceinline__ u64 fma2(u64 a, u64 b, u64 c){
    u64 d; asm("fma.rn.f32x2 %0, %1, %2, %3;" : "=l"(d) : "l"(a), "l"(b), "l"(c)); return d;
}

__device__ __forceinline__ void lrelu3(const float p[3], const float d[3], float o[3]){
    float dot = fmaf(p[0], d[0], fmaf(p[1], d[1], p[2]*d[2]));
    float dn  = fmaf(d[0], d[0], fmaf(d[1], d[1], d[2]*d[2]));
    float f = (dot >= 0.f) ? 0.f : dot * __fdividef(1.f, dn + EPSV);
    o[0] = fmaf(-f, d[0], p[0]);
    o[1] = fmaf(-f, d[1], p[1]);
    o[2] = fmaf(-f, d[2], p[2]);
}

// ---------------- fused VN GEMM ----------------
// MODE 0: Y[n,o,:] = Wf x                      (vn_linear)
// MODE 1: dual (p=Wf x, d=Wd x) + leaky-relu   (VNLinearLeakyReLU, ns=0)
// MODE 2: d = Wf x ; Y[n,o] = sum_i x[n,o,i]*d[n,o,i]   (dot for seg_max)
// MODE 3: MODE1 + per-segment bias added to p and d (concat folded to bias)
// Block: 32 points, 128 out-channel chunk (grid.y), 256 threads.
// Thread: 2 points x 8 outs (4 f32x2 pairs) x 3 comps.
template<int CIN, int MODE>
__global__ void __launch_bounds__(256, 1)
vn_gemm(const float* __restrict__ X, const float* __restrict__ Wfg,
        const float* __restrict__ Wdg,
        const float* __restrict__ biasF, const float* __restrict__ biasD,
        float* __restrict__ Y, int coTotal, int wStride, int segLen)
{
    constexpr bool DUAL = (MODE == 1 || MODE == 3);
    constexpr int WS = 130;            // padded SMEM weight row stride [c][o]
    extern __shared__ float sm[];
    float* Wfs = sm;
    float* Wds = DUAL ? (sm + CIN*WS) : sm;
    float* Xs  = sm + (DUAL ? 2 : 1)*CIN*WS;   // [CIN*3][32] with xor-skew

    const int t = threadIdx.x;
    const size_t nBase = (size_t)blockIdx.x * 32;
    const int oBase = blockIdx.y * 128;

    // ---- load weight chunk: global row-major [o][c] -> smem [c][o] (padded) ----
    constexpr int C4 = CIN / 4;
    for (int idx = t; idx < 128*C4; idx += 256){
        int o  = idx / C4;
        int c4 = (idx - o*C4) * 4;
        const float4 vf = *(const float4*)(Wfg + (size_t)(oBase + o)*wStride + c4);
        Wfs[(c4+0)*WS + o] = vf.x; Wfs[(c4+1)*WS + o] = vf.y;
        Wfs[(c4+2)*WS + o] = vf.z; Wfs[(c4+3)*WS + o] = vf.w;
        if (DUAL){
            const float4 vd = *(const float4*)(Wdg + (size_t)(oBase + o)*wStride + c4);
            Wds[(c4+0)*WS + o] = vd.x; Wds[(c4+1)*WS + o] = vd.y;
            Wds[(c4+2)*WS + o] = vd.z; Wds[(c4+3)*WS + o] = vd.w;
        }
    }
    // ---- load X tile [32 pts][CIN*3] -> smem [ci][32] with xor skew ----
    constexpr int CI3 = CIN*3;
    constexpr int X4  = CI3 / 4;
    for (int idx = t; idx < 32*X4; idx += 256){
        int p  = idx / X4;
        int ci = (idx - p*X4) * 4;
        const float4 v = *(const float4*)(X + (nBase + p)*(size_t)CI3 + ci);
        Xs[(ci+0)*32 + (((ci+0)&31) ^ p)] = v.x;
        Xs[(ci+1)*32 + (((ci+1)&31) ^ p)] = v.y;
        Xs[(ci+2)*32 + (((ci+2)&31) ^ p)] = v.z;
        Xs[(ci+3)*32 + (((ci+3)&31) ^ p)] = v.w;
    }
    __syncthreads();

    const int otid = t & 15;
    const int ptid = t >> 4;
    const int pt0  = 2*ptid;

    u64 aP[2][4][3];
    u64 aD[2][4][3];
    #pragma unroll
    for (int pp = 0; pp < 2; pp++)
        #pragma unroll
        for (int jj = 0; jj < 4; jj++)
            #pragma unroll
            for (int i = 0; i < 3; i++){
                aP[pp][jj][i] = 0ull;
                if (DUAL) aD[pp][jj][i] = 0ull;
            }

    const float* wfb = Wfs + 2*otid;
    const float* wdb = Wds + 2*otid;

    #pragma unroll 4
    for (int c = 0; c < CIN; c++){
        const int ci = 3*c;
        u64 xs2[2][3];
        #pragma unroll
        for (int i = 0; i < 3; i++){
            int r = (ci + i)*32, m = (ci + i) & 31;
            float xa = Xs[r + (m ^ pt0)];
            float xb = Xs[r + (m ^ (pt0 + 1))];
            xs2[0][i] = pack2(xa, xa);
            xs2[1][i] = pack2(xb, xb);
        }
        const float* wf = wfb + c*WS;
        const float* wd = wdb + c*WS;
        #pragma unroll
        for (int jj = 0; jj < 4; jj++){
            u64 w2 = *(const u64*)(wf + 32*jj);
            #pragma unroll
            for (int pp = 0; pp < 2; pp++)
                #pragma unroll
                for (int i = 0; i < 3; i++)
                    aP[pp][jj][i] = fma2(xs2[pp][i], w2, aP[pp][jj][i]);
            if (DUAL){
                u64 wd2 = *(const u64*)(wd + 32*jj);
                #pragma unroll
                for (int pp = 0; pp < 2; pp++)
                    #pragma unroll
                    for (int i = 0; i < 3; i++)
                        aD[pp][jj][i] = fma2(xs2[pp][i], wd2, aD[pp][jj][i]);
            }
        }
    }

    // ---- epilogue ----
    const size_t co3 = (size_t)coTotal * 3;
    int seg = 0;
    if (MODE == 3) seg = (int)(nBase / (size_t)segLen);

    #pragma unroll
    for (int pp = 0; pp < 2; pp++){
        const size_t n = nBase + pt0 + pp;
        #pragma unroll
        for (int jj = 0; jj < 4; jj++){
            const int o0 = 2*otid + 32*jj;
            float pa[3], pb[3];
            #pragma unroll
            for (int i = 0; i < 3; i++) unpack2(aP[pp][jj][i], pa[i], pb[i]);

            if (MODE == 0){
                float2* yp = (float2*)(Y + n*co3 + (size_t)(oBase + o0)*3);
                yp[0] = make_float2(pa[0], pa[1]);
                yp[1] = make_float2(pa[2], pb[0]);
                yp[2] = make_float2(pb[1], pb[2]);
            } else if (MODE == 2){
                float dta = 0.f, dtb = 0.f;
                #pragma unroll
                for (int i = 0; i < 3; i++){
                    int cia = (oBase + o0)*3 + i;
                    int cib = cia + 3;
                    dta = fmaf(pa[i], Xs[cia*32 + ((cia & 31) ^ (pt0 + pp))], dta);
                    dtb = fmaf(pb[i], Xs[cib*32 + ((cib & 31) ^ (pt0 + pp))], dtb);
                }
                *(float2*)(Y + n*(size_t)coTotal + (oBase + o0)) = make_float2(dta, dtb);
            } else {
                float da[3], db[3];
                #pragma unroll
                for (int i = 0; i < 3; i++) unpack2(aD[pp][jj][i], da[i], db[i]);
                if (MODE == 3){
                    const float* bfp = biasF + ((size_t)seg*coTotal + oBase + o0)*3;
                    const float* bdp = biasD + ((size_t)seg*coTotal + oBase + o0)*3;
                    #pragma unroll
                    for (int i = 0; i < 3; i++){
                        pa[i] += bfp[i];   pb[i] += bfp[3 + i];
                        da[i] += bdp[i];   db[i] += bdp[3 + i];
                    }
                }
                float oa[3], ob[3];
                lrelu3(pa, da, oa);
                lrelu3(pb, db, ob);
                float2* yp = (float2*)(Y + n*co3 + (size_t)(oBase + o0)*3);
                yp[0] = make_float2(oa[0], oa[1]);
                yp[1] = make_float2(oa[2], ob[0]);
                yp[2] = make_float2(ob[1], ob[2]);
            }
        }
    }
}

// ---------------- segment argmax + gather (contiguous equal segments) ----------------
template<int C>
__global__ void k_segmax(const float* __restrict__ dotv, const float* __restrict__ V,
                         float* __restrict__ pooled, int segLen)
{
    __shared__ float sv[8][32];
    __shared__ int   si[8][32];
    const int ci = threadIdx.x & 31, ri = threadIdx.x >> 5;
    const int c = blockIdx.y * 32 + ci;
    const int s = blockIdx.x;
    const size_t base = (size_t)s * segLen;
    const int per = segLen >> 3;
    const int r0 = ri * per;
    float best = -3.402823466e38f; int bi = 0;
    const float* dp = dotv + (base + r0)*(size_t)C + c;
    for (int r = 0; r < per; r++){
        float v = dp[(size_t)r * C];
        if (v > best){ best = v; bi = r0 + r; }   // strict > keeps smallest index
    }
    sv[ri][ci] = best; si[ri][ci] = bi;
    __syncthreads();
    if (ri == 0){
        #pragma unroll
        for (int k = 1; k < 8; k++){
            float v = sv[k][ci];
            if (v > best){ best = v; bi = si[k][ci]; }  // ascending ranges: min-index tiebreak
        }
        const size_t row = base + bi;
        const float* xp = V + (row*(size_t)C + c)*3;
        float* op = pooled + ((size_t)s*C + c)*3;
        op[0] = xp[0]; op[1] = xp[1]; op[2] = xp[2];
    }
}

// ---------------- small VNLeakyReLU over [32, C, 3] ----------------
template<int C>
__global__ void k_relu_small(const float* __restrict__ Xin, const float* __restrict__ Wr,
                             float* __restrict__ out)
{
    __shared__ float xs[C*3];
    const int s = blockIdx.x, c = threadIdx.x;
    for (int idx = c; idx < C*3; idx += C) xs[idx] = Xin[(size_t)s*C*3 + idx];
    __syncthreads();
    float d0 = 0.f, d1 = 0.f, d2 = 0.f;
    const float* wr = Wr + (size_t)c * C;
    for (int k = 0; k < C; k++){
        float w = wr[k];
        d0 = fmaf(w, xs[k*3 + 0], d0);
        d1 = fmaf(w, xs[k*3 + 1], d1);
        d2 = fmaf(w, xs[k*3 + 2], d2);
    }
    float x0 = xs[c*3], x1 = xs[c*3 + 1], x2 = xs[c*3 + 2];
    float dot = x0*d0 + x1*d1 + x2*d2;
    float dn  = d0*d0 + d1*d1 + d2*d2;
    float f = (dot >= 0.f) ? 0.f : dot * __fdividef(1.f, dn + EPSV);
    float* op = out + ((size_t)s*C + c)*3;
    op[0] = fmaf(-f, d0, x0);
    op[1] = fmaf(-f, d1, x1);
    op[2] = fmaf(-f, d2, x2);
}

// ---------------- per-segment bias: W4*[:,128:256] @ r3[s] ----------------
__global__ void k_bias(const float* __restrict__ r3, const float* __restrict__ W4f,
                       const float* __restrict__ W4d,
                       float* __restrict__ bf, float* __restrict__ bd)
{
    __shared__ float xs[128*3];
    const int s = blockIdx.x, o = threadIdx.x;   // 256 threads
    for (int idx = o; idx < 384; idx += 256) xs[idx] = r3[(size_t)s*384 + idx];
    __syncthreads();
    float f0=0.f,f1=0.f,f2=0.f,e0=0.f,e1=0.f,e2=0.f;
    const float* wf = W4f + (size_t)o*256 + 128;
    const float* wd = W4d + (size_t)o*256 + 128;
    for (int h = 0; h < 128; h++){
        float a = wf[h], b = wd[h];
        f0 = fmaf(a, xs[h*3+0], f0); f1 = fmaf(a, xs[h*3+1], f1); f2 = fmaf(a, xs[h*3+2], f2);
        e0 = fmaf(b, xs[h*3+0], e0); e1 = fmaf(b, xs[h*3+1], e1); e2 = fmaf(b, xs[h*3+2], e2);
    }
    const size_t base = ((size_t)s*256 + o)*3;
    bf[base] = f0; bf[base+1] = f1; bf[base+2] = f2;
    bd[base] = e0; bd[base+1] = e1; bd[base+2] = e2;
}

// ---------------- launch ----------------
extern "C" void kernel_launch(void* const* d_in, const int* in_sizes, int n_in,
                              void* d_out, int out_size)
{
    const float* pos = (const float*)d_in[0];
    const float* W1f = (const float*)d_in[2];
    const float* W1d = (const float*)d_in[3];
    const float* W2f = (const float*)d_in[4];
    const float* W2d = (const float*)d_in[5];
    const float* W3  = (const float*)d_in[6];
    const float* Wd1 = (const float*)d_in[7];
    const float* Wr3 = (const float*)d_in[8];
    const float* W4f = (const float*)d_in[9];
    const float* W4d = (const float*)d_in[10];
    const float* W5  = (const float*)d_in[11];
    const float* Wd2 = (const float*)d_in[12];
    const float* Wr5 = (const float*)d_in[13];

    const int N = in_sizes[0] / 384;
    const int segLen = N / 32;
    const int gb = N / 32;

    float *pool,*p1,*r3,*p2,*bf,*bd;
    cudaGetSymbolAddress((void**)&pool, g_pool);
    cudaGetSymbolAddress((void**)&p1, g_pool1);
    cudaGetSymbolAddress((void**)&r3, g_r3);
    cudaGetSymbolAddress((void**)&p2, g_pool2);
    cudaGetSymbolAddress((void**)&bf, g_bf);
    cudaGetSymbolAddress((void**)&bd, g_bd);

    // aliased scratch layout (see g_pool comment)
    float* b1  = pool;
    float* b2  = pool + (size_t)N*384;
    float* dt1 = pool + (size_t)N*768;
    float* c1  = pool;
    float* c2  = pool + (size_t)N*768;
    float* dt2 = pool + (size_t)N*1536;

    const int S_D128 = 4*(2*128*130 + 128*96);   // 182272 B
    const int S_S128 = 4*(  128*130 + 128*96);   // 115712 B
    const int S_S256 = 4*(  256*130 + 256*96);   // 231424 B

    cudaFuncSetAttribute(vn_gemm<128,1>, cudaFuncAttributeMaxDynamicSharedMemorySize, S_D128);
    cudaFuncSetAttribute(vn_gemm<128,0>, cudaFuncAttributeMaxDynamicSharedMemorySize, S_S128);
    cudaFuncSetAttribute(vn_gemm<128,2>, cudaFuncAttributeMaxDynamicSharedMemorySize, S_S128);
    cudaFuncSetAttribute(vn_gemm<128,3>, cudaFuncAttributeMaxDynamicSharedMemorySize, S_D128);
    cudaFuncSetAttribute(vn_gemm<256,0>, cudaFuncAttributeMaxDynamicSharedMemorySize, S_S256);
    cudaFuncSetAttribute(vn_gemm<256,2>, cudaFuncAttributeMaxDynamicSharedMemorySize, S_S256);

    dim3 blk(256);

    // stage 1
    vn_gemm<128,1><<<dim3(gb,1), blk, S_D128>>>(pos, W1f, W1d, nullptr, nullptr, b1, 128, 128, segLen);
    vn_gemm<128,1><<<dim3(gb,1), blk, S_D128>>>(b1,  W2f, W2d, nullptr, nullptr, b2, 128, 128, segLen);
    vn_gemm<128,0><<<dim3(gb,1), blk, S_S128>>>(b2,  W3,  nullptr, nullptr, nullptr, b1, 128, 128, segLen);
    vn_gemm<128,2><<<dim3(gb,1), blk, S_S128>>>(b1,  Wd1, nullptr, nullptr, nullptr, dt1, 128, 128, segLen);
    k_segmax<128><<<dim3(32,4), dim3(256)>>>(dt1, b1, p1, segLen);
    k_relu_small<128><<<32, 128>>>(p1, Wr3, r3);

    // stage 2 (concat folded into per-segment bias); c1/c2 overwrite dead stage-1 buffers
    k_bias<<<32, 256>>>(r3, W4f, W4d, bf, bd);
    vn_gemm<128,3><<<dim3(gb,2), blk, S_D128>>>(pos, W4f, W4d, bf, bd, c1, 256, 256, segLen);
    vn_gemm<256,0><<<dim3(gb,2), blk, S_S256>>>(c1, W5,  nullptr, nullptr, nullptr, c2, 256, 256, segLen);
    vn_gemm<256,2><<<dim3(gb,2), blk, S_S256>>>(c2, Wd2, nullptr, nullptr, nullptr, dt2, 256, 256, segLen);
    k_segmax<256><<<dim3(32,8), dim3(256)>>>(dt2, c2, p2, segLen);
    k_relu_small<256><<<32, 256>>>(p2, Wr5, (float*)d_out);
}

// round 4
// speedup vs baseline: 1.1491x; 1.1491x over previous
#include <cuda_runtime.h>

#define EPSV 1e-7f
typedef unsigned long long u64;

// ---------------- scratch: single aliased pool (no allocs) ----------------
#define N_MAX 131072
// stage 1:  b1 = pool+0      [N*384]   (layout [n][3][128])
//           b2 = pool+N*384  [N*384]
//           dt1= pool+N*768  [N*128]
// stage 2:  c1 = pool+0      [N*768]   (layout [n][3][256])
//           c2 = pool+N*768  [N*768]
//           dt2= pool+N*1536 [N*256]
__device__ __align__(256) float g_pool[(size_t)N_MAX*1792];
__device__ __align__(256) float g_pool1[32*128*3];
__device__ __align__(256) float g_r3[32*128*3];
__device__ __align__(256) float g_pool2[32*256*3];
__device__ __align__(256) float g_bf[32*256*3];
__device__ __align__(256) float g_bd[32*256*3];

// ---------------- f32x2 packed helpers ----------------
__device__ __forceinline__ void unpack2(u64 v, float& lo, float& hi){
    asm("mov.b64 {%0, %1}, %2;" : "=f"(lo), "=f"(hi) : "l"(v));
}
__device__ __forceinline__ u64 fma2(u64 a, u64 b, u64 c){
    u64 d; asm("fma.rn.f32x2 %0, %1, %2, %3;" : "=l"(d) : "l"(a), "l"(b), "l"(c)); return d;
}

__device__ __forceinline__ void lrelu3(const float p[3], const float d[3], float o[3]){
    float dot = fmaf(p[0], d[0], fmaf(p[1], d[1], p[2]*d[2]));
    float dn  = fmaf(d[0], d[0], fmaf(d[1], d[1], d[2]*d[2]));
    float f = (dot >= 0.f) ? 0.f : dot * __fdividef(1.f, dn + EPSV);
    o[0] = fmaf(-f, d[0], p[0]);
    o[1] = fmaf(-f, d[1], p[1]);
    o[2] = fmaf(-f, d[2], p[2]);
}

// ---------------- fused VN GEMM, K packed into f32x2 lanes ----------------
// Intermediate activations are stored [n][3][C] (component-major) so that
// (c, c+1) pairs are contiguous for LDS.64. Weights [o][c] used as-is.
// MODE 0: Y = Wf x                          (vn_linear), out [n][3][CO]
// MODE 1: dual p=Wf x, d=Wd x + leakyrelu   out [n][3][CO]
// MODE 2: d = Wf x ; Y[n,o] = sum_i x[n,o,i]*d[n,o,i]  out [n][CO]
// MODE 3: MODE1 + per-segment bias (concat folded into bias)
// Block: 256 threads = 16 otids x 16 ptgroups; 2 pts/thread, NO outs/thread.
// CHUNK = 16*NO output channels per grid.y. `tiles` tiles of 32 points per block.
// TR: input is external [n][CIN][3] (pos) and must be transposed at tile load.
template<int CIN, int MODE, int NO, bool TR>
__global__ void __launch_bounds__(256, 1)
vn_gemm(const float* __restrict__ X, const float* __restrict__ Wfg,
        const float* __restrict__ Wdg,
        const float* __restrict__ biasF, const float* __restrict__ biasD,
        float* __restrict__ Y, int coTotal, int wStride, int tiles, int segLen)
{
    constexpr bool DUAL = (MODE == 1 || MODE == 3);
    constexpr int CHUNK = NO * 16;
    constexpr int WS = CIN + 2;        // padded weight row stride
    constexpr int XS = 3*CIN + 2;      // padded x row stride (per point)
    extern __shared__ float sm[];
    float* Wfs = sm;
    float* Wds = sm + CHUNK*WS;
    float* Xs  = sm + (DUAL ? 2 : 1)*CHUNK*WS;   // [32 pts][XS]

    const int t = threadIdx.x;
    const int oBase = blockIdx.y * CHUNK;
    const size_t nBlock = (size_t)blockIdx.x * (32*tiles);

    // ---- load weight chunk, straight rows ----
    for (int idx = t; idx < CHUNK*(CIN/4); idx += 256){
        int o = idx / (CIN/4);
        int c = (idx - o*(CIN/4)) * 4;
        float4 v = *(const float4*)(Wfg + (size_t)(oBase + o)*wStride + c);
        *(float2*)(Wfs + o*WS + c)     = make_float2(v.x, v.y);
        *(float2*)(Wfs + o*WS + c + 2) = make_float2(v.z, v.w);
        if (DUAL){
            float4 u = *(const float4*)(Wdg + (size_t)(oBase + o)*wStride + c);
            *(float2*)(Wds + o*WS + c)     = make_float2(u.x, u.y);
            *(float2*)(Wds + o*WS + c + 2) = make_float2(u.z, u.w);
        }
    }

    const int otid = t & 15;
    const int pg   = t >> 4;
    const int pt0  = 2*pg;

    for (int tl = 0; tl < tiles; tl++){
        const size_t nBase = nBlock + tl*32;
        __syncthreads();   // previous tile fully consumed before overwrite
        if (TR){
            // external [n][CIN][3] -> Xs[pt][i*CIN + c]
            for (int idx = t; idx < 32*(CIN/4); idx += 256){
                int pt = idx / (CIN/4);
                int c4 = (idx - pt*(CIN/4)) * 4;
                const float* gp = X + (nBase + pt)*(size_t)(3*CIN) + c4*3;
                float4 f0 = *(const float4*)(gp);
                float4 f1 = *(const float4*)(gp + 4);
                float4 f2 = *(const float4*)(gp + 8);
                float v[12] = {f0.x,f0.y,f0.z,f0.w,f1.x,f1.y,f1.z,f1.w,f2.x,f2.y,f2.z,f2.w};
                float* xr = Xs + pt*XS;
                #pragma unroll
                for (int k = 0; k < 12; k++){
                    int cc = c4 + k/3, ii = k - 3*(k/3);
                    xr[ii*CIN + cc] = v[k];
                }
            }
        } else {
            // internal [n][3][CIN] -> straight copy
            for (int idx = t; idx < 32*(3*CIN/4); idx += 256){
                int pt = idx / (3*CIN/4);
                int q  = (idx - pt*(3*CIN/4)) * 4;
                float4 v = *(const float4*)(X + (nBase + pt)*(size_t)(3*CIN) + q);
                *(float2*)(Xs + pt*XS + q)     = make_float2(v.x, v.y);
                *(float2*)(Xs + pt*XS + q + 2) = make_float2(v.z, v.w);
            }
        }
        __syncthreads();

        u64 aP[NO][2][3];
        u64 aD[DUAL ? NO : 1][2][3];
        #pragma unroll
        for (int j = 0; j < NO; j++)
            #pragma unroll
            for (int p = 0; p < 2; p++)
                #pragma unroll
                for (int i = 0; i < 3; i++){
                    aP[j][p][i] = 0ull;
                    if (DUAL) aD[j][p][i] = 0ull;
                }

        const float* x0 = Xs + pt0*XS;
        const float* x1 = x0 + XS;

        #pragma unroll 2
        for (int cp = 0; cp < CIN/2; cp++){
            const int c = 2*cp;
            u64 xv[2][3];
            #pragma unroll
            for (int i = 0; i < 3; i++){
                xv[0][i] = *(const u64*)(x0 + i*CIN + c);
                xv[1][i] = *(const u64*)(x1 + i*CIN + c);
            }
            #pragma unroll
            for (int j = 0; j < NO; j++){
                u64 w2 = *(const u64*)(Wfs + (otid + 16*j)*WS + c);
                #pragma unroll
                for (int p = 0; p < 2; p++)
                    #pragma unroll
                    for (int i = 0; i < 3; i++)
                        aP[j][p][i] = fma2(xv[p][i], w2, aP[j][p][i]);
                if (DUAL){
                    u64 d2 = *(const u64*)(Wds + (otid + 16*j)*WS + c);
                    #pragma unroll
                    for (int p = 0; p < 2; p++)
                        #pragma unroll
                        for (int i = 0; i < 3; i++)
                            aD[j][p][i] = fma2(xv[p][i], d2, aD[j][p][i]);
                }
            }
        }

        // ---- epilogue ----
        const size_t co3 = 3*(size_t)coTotal;
        int seg = 0;
        if (MODE == 3) seg = (int)(nBase / (size_t)segLen);

        #pragma unroll
        for (int j = 0; j < NO; j++){
            const int og = oBase + otid + 16*j;
            #pragma unroll
            for (int p = 0; p < 2; p++){
                const size_t n = nBase + pt0 + p;
                if (MODE == 0){
                    #pragma unroll
                    for (int i = 0; i < 3; i++){
                        float lo, hi; unpack2(aP[j][p][i], lo, hi);
                        Y[n*co3 + (size_t)i*coTotal + og] = lo + hi;
                    }
                } else if (MODE == 2){
                    const float* xr = Xs + (pt0 + p)*XS;
                    float dot = 0.f;
                    #pragma unroll
                    for (int i = 0; i < 3; i++){
                        float lo, hi; unpack2(aP[j][p][i], lo, hi);
                        dot = fmaf(lo + hi, xr[i*CIN + og], dot);
                    }
                    Y[n*(size_t)coTotal + og] = dot;
                } else {
                    float pv[3], dv[3], ov[3];
                    #pragma unroll
                    for (int i = 0; i < 3; i++){
                        float lo, hi;
                        unpack2(aP[j][p][i], lo, hi); pv[i] = lo + hi;
                        unpack2(aD[j][p][i], lo, hi); dv[i] = lo + hi;
                    }
                    if (MODE == 3){
                        const float* bfp = biasF + ((size_t)seg*coTotal + og)*3;
                        const float* bdp = biasD + ((size_t)seg*coTotal + og)*3;
                        #pragma unroll
                        for (int i = 0; i < 3; i++){ pv[i] += bfp[i]; dv[i] += bdp[i]; }
                    }
                    lrelu3(pv, dv, ov);
                    #pragma unroll
                    for (int i = 0; i < 3; i++)
                        Y[n*co3 + (size_t)i*coTotal + og] = ov[i];
                }
            }
        }
    }
}

// ---------------- segment argmax + gather; V layout [n][3][C] ----------------
template<int C>
__global__ void k_segmax(const float* __restrict__ dotv, const float* __restrict__ V,
                         float* __restrict__ pooled, int segLen)
{
    __shared__ float sv[8][32];
    __shared__ int   si[8][32];
    const int ci = threadIdx.x & 31, ri = threadIdx.x >> 5;
    const int c = blockIdx.y * 32 + ci;
    const int s = blockIdx.x;
    const size_t base = (size_t)s * segLen;
    const int per = segLen >> 3;
    const int r0 = ri * per;
    float best = -3.402823466e38f; int bi = 0;
    const float* dp = dotv + (base + r0)*(size_t)C + c;
    for (int r = 0; r < per; r++){
        float v = dp[(size_t)r * C];
        if (v > best){ best = v; bi = r0 + r; }   // strict > keeps smallest index
    }
    sv[ri][ci] = best; si[ri][ci] = bi;
    __syncthreads();
    if (ri == 0){
        #pragma unroll
        for (int k = 1; k < 8; k++){
            float v = sv[k][ci];
            if (v > best){ best = v; bi = si[k][ci]; }
        }
        const size_t row = base + bi;
        const float* xp = V + row*(size_t)(3*C) + c;
        float* op = pooled + ((size_t)s*C + c)*3;
        op[0] = xp[0]; op[1] = xp[C]; op[2] = xp[2*C];
    }
}

// ---------------- small VNLeakyReLU over [32, C, 3] ----------------
template<int C>
__global__ void k_relu_small(const float* __restrict__ Xin, const float* __restrict__ Wr,
                             float* __restrict__ out)
{
    __shared__ float xs[C*3];
    const int s = blockIdx.x, c = threadIdx.x;
    for (int idx = c; idx < C*3; idx += C) xs[idx] = Xin[(size_t)s*C*3 + idx];
    __syncthreads();
    float d0 = 0.f, d1 = 0.f, d2 = 0.f;
    const float* wr = Wr + (size_t)c * C;
    for (int k = 0; k < C; k++){
        float w = wr[k];
        d0 = fmaf(w, xs[k*3 + 0], d0);
        d1 = fmaf(w, xs[k*3 + 1], d1);
        d2 = fmaf(w, xs[k*3 + 2], d2);
    }
    float x0 = xs[c*3], x1 = xs[c*3 + 1], x2 = xs[c*3 + 2];
    float dot = x0*d0 + x1*d1 + x2*d2;
    float dn  = d0*d0 + d1*d1 + d2*d2;
    float f = (dot >= 0.f) ? 0.f : dot * __fdividef(1.f, dn + EPSV);
    float* op = out + ((size_t)s*C + c)*3;
    op[0] = fmaf(-f, d0, x0);
    op[1] = fmaf(-f, d1, x1);
    op[2] = fmaf(-f, d2, x2);
}

// ---------------- per-segment bias: W4*[:,128:256] @ r3[s] ----------------
__global__ void k_bias(const float* __restrict__ r3, const float* __restrict__ W4f,
                       const float* __restrict__ W4d,
                       float* __restrict__ bf, float* __restrict__ bd)
{
    __shared__ float xs[128*3];
    const int s = blockIdx.x, o = threadIdx.x;   // 256 threads
    for (int idx = o; idx < 384; idx += 256) xs[idx] = r3[(size_t)s*384 + idx];
    __syncthreads();
    float f0=0.f,f1=0.f,f2=0.f,e0=0.f,e1=0.f,e2=0.f;
    const float* wf = W4f + (size_t)o*256 + 128;
    const float* wd = W4d + (size_t)o*256 + 128;
    for (int h = 0; h < 128; h++){
        float a = wf[h], b = wd[h];
        f0 = fmaf(a, xs[h*3+0], f0); f1 = fmaf(a, xs[h*3+1], f1); f2 = fmaf(a, xs[h*3+2], f2);
        e0 = fmaf(b, xs[h*3+0], e0); e1 = fmaf(b, xs[h*3+1], e1); e2 = fmaf(b, xs[h*3+2], e2);
    }
    const size_t base = ((size_t)s*256 + o)*3;
    bf[base] = f0; bf[base+1] = f1; bf[base+2] = f2;
    bd[base] = e0; bd[base+1] = e1; bd[base+2] = e2;
}

// ---------------- launch ----------------
extern "C" void kernel_launch(void* const* d_in, const int* in_sizes, int n_in,
                              void* d_out, int out_size)
{
    const float* pos = (const float*)d_in[0];
    const float* W1f = (const float*)d_in[2];
    const float* W1d = (const float*)d_in[3];
    const float* W2f = (const float*)d_in[4];
    const float* W2d = (const float*)d_in[5];
    const float* W3  = (const float*)d_in[6];
    const float* Wd1 = (const float*)d_in[7];
    const float* Wr3 = (const float*)d_in[8];
    const float* W4f = (const float*)d_in[9];
    const float* W4d = (const float*)d_in[10];
    const float* W5  = (const float*)d_in[11];
    const float* Wd2 = (const float*)d_in[12];
    const float* Wr5 = (const float*)d_in[13];

    const int N = in_sizes[0] / 384;
    const int segLen = N / 32;
    const int TILES = 4;
    const int gb = N / (32*TILES);

    float *pool,*p1,*r3,*p2,*bf,*bd;
    cudaGetSymbolAddress((void**)&pool, g_pool);
    cudaGetSymbolAddress((void**)&p1, g_pool1);
    cudaGetSymbolAddress((void**)&r3, g_r3);
    cudaGetSymbolAddress((void**)&p2, g_pool2);
    cudaGetSymbolAddress((void**)&bf, g_bf);
    cudaGetSymbolAddress((void**)&bd, g_bd);

    float* b1  = pool;
    float* b2  = pool + (size_t)N*384;
    float* dt1 = pool + (size_t)N*768;
    float* c1  = pool;
    float* c2  = pool + (size_t)N*768;
    float* dt2 = pool + (size_t)N*1536;

    // smem bytes: (DUAL?2:1)*CHUNK*(CIN+2) + 32*(3*CIN+2), floats
    const int S_DUAL128 = 4*(2*64*130 + 32*386);    // 115,968
    const int S_SNG128  = 4*(128*130 + 32*386);     // 115,968
    const int S_SNG256  = 4*(64*258 + 32*770);      // 164,608

    cudaFuncSetAttribute(vn_gemm<128,1,4,true >, cudaFuncAttributeMaxDynamicSharedMemorySize, S_DUAL128);
    cudaFuncSetAttribute(vn_gemm<128,1,4,false>, cudaFuncAttributeMaxDynamicSharedMemorySize, S_DUAL128);
    cudaFuncSetAttribute(vn_gemm<128,0,8,false>, cudaFuncAttributeMaxDynamicSharedMemorySize, S_SNG128);
    cudaFuncSetAttribute(vn_gemm<128,2,8,false>, cudaFuncAttributeMaxDynamicSharedMemorySize, S_SNG128);
    cudaFuncSetAttribute(vn_gemm<128,3,4,true >, cudaFuncAttributeMaxDynamicSharedMemorySize, S_DUAL128);
    cudaFuncSetAttribute(vn_gemm<256,0,4,false>, cudaFuncAttributeMaxDynamicSharedMemorySize, S_SNG256);
    cudaFuncSetAttribute(vn_gemm<256,2,4,false>, cudaFuncAttributeMaxDynamicSharedMemorySize, S_SNG256);

    dim3 blk(256);

    // stage 1
    vn_gemm<128,1,4,true ><<<dim3(gb,2), blk, S_DUAL128>>>(pos, W1f, W1d, nullptr, nullptr, b1, 128, 128, TILES, segLen);
    vn_gemm<128,1,4,false><<<dim3(gb,2), blk, S_DUAL128>>>(b1,  W2f, W2d, nullptr, nullptr, b2, 128, 128, TILES, segLen);
    vn_gemm<128,0,8,false><<<dim3(gb,1), blk, S_SNG128 >>>(b2,  W3,  nullptr, nullptr, nullptr, b1, 128, 128, TILES, segLen);
    vn_gemm<128,2,8,false><<<dim3(gb,1), blk, S_SNG128 >>>(b1,  Wd1, nullptr, nullptr, nullptr, dt1, 128, 128, TILES, segLen);
    k_segmax<128><<<dim3(32,4), dim3(256)>>>(dt1, b1, p1, segLen);
    k_relu_small<128><<<32, 128>>>(p1, Wr3, r3);

    // stage 2 (concat folded into per-segment bias)
    k_bias<<<32, 256>>>(r3, W4f, W4d, bf, bd);
    vn_gemm<128,3,4,true ><<<dim3(gb,4), blk, S_DUAL128>>>(pos, W4f, W4d, bf, bd, c1, 256, 256, TILES, segLen);
    vn_gemm<256,0,4,false><<<dim3(gb,4), blk, S_SNG256 >>>(c1, W5,  nullptr, nullptr, nullptr, c2, 256, 256, TILES, segLen);
    vn_gemm<256,2,4,false><<<dim3(gb,4), blk, S_SNG256 >>>(c2, Wd2, nullptr, nullptr, nullptr, dt2, 256, 256, TILES, segLen);
    k_segmax<256><<<dim3(32,8), dim3(256)>>>(dt2, c2, p2, segLen);
    k_relu_small<256><<<32, 256>>>(p2, Wr5, (float*)d_out);
}

// round 14
// speedup vs baseline: 1.2521x; 1.0896x over previous
// GlobalEmdModelVn — 3xTF32 mma.sync pipeline (rev R14; semantically identical to R12/R13)
#include <cuda_runtime.h>
#include <cstdint>

#define EPSV 1e-7f
typedef unsigned long long u64;
typedef unsigned int u32;

// ---------------- scratch (static; no allocs) ----------------
#define N_MAX 131072
#define UNIT ((size_t)3*N_MAX*128)    // 50,331,648 floats = one [3N x 128] matrix
__device__ __align__(1024) float g_scr[6*UNIT];   // 1.21 GB aliased scratch
__device__ __align__(1024) float g_posT[UNIT];    // pos transposed [n][3][128]
__device__ __align__(256)  float g_pool1[32*128*3];
__device__ __align__(256)  float g_r3[32*128*3];
__device__ __align__(256)  float g_pool2[32*256*3];
__device__ __align__(256)  float g_bf[32*256*3];
__device__ __align__(256)  float g_bd[32*256*3];

// ---------------- helpers ----------------
// tf32 round-to-nearest-ties-away (bitwise equivalent of cvt.rna.tf32.f32):
// add half-ulp of the 19-bit format to the magnitude bits, then truncate.
static __device__ __forceinline__ u32 tf32hi(float x){
    u32 b = __float_as_uint(x);
    return (b + 0x1000u) & 0xFFFFE000u;
}
// returns lo = tf32(x - as_float(hi))
static __device__ __forceinline__ u32 tf32lo(float x, u32 hi){
    u32 b = __float_as_uint(x - __uint_as_float(hi));
    return (b + 0x1000u) & 0xFFFFE000u;
}
static __device__ __forceinline__ void mma8(float* c, const u32* a, const u32* b){
    asm volatile("mma.sync.aligned.m16n8k8.row.col.f32.tf32.tf32.f32 "
        "{%0,%1,%2,%3}, {%4,%5,%6,%7}, {%8,%9}, {%0,%1,%2,%3};"
        : "+f"(c[0]), "+f"(c[1]), "+f"(c[2]), "+f"(c[3])
        : "r"(a[0]), "r"(a[1]), "r"(a[2]), "r"(a[3]), "r"(b[0]), "r"(b[1]));
}

__device__ __forceinline__ void lrelu3(const float p[3], const float d[3], float o[3]){
    float dot = fmaf(p[0], d[0], fmaf(p[1], d[1], p[2]*d[2]));
    float dn  = fmaf(d[0], d[0], fmaf(d[1], d[1], d[2]*d[2]));
    float f = (dot >= 0.f) ? 0.f : dot * __fdividef(1.f, dn + EPSV);
    o[0] = fmaf(-f, d[0], p[0]);
    o[1] = fmaf(-f, d[1], p[1]);
    o[2] = fmaf(-f, d[2], p[2]);
}

// ---------------- 3xTF32 mma.sync GEMM ----------------
// Y[m][n0+n] = sum_k A[m][k] * W[n0+n][k], fp32 in/out, split-precision 3-pass
// (hi*hi + hi*lo + lo*hi) for fp32-grade accuracy on tensor cores.
// Block: 128 threads, tile 64(M) x 128(N), K staged 32 at a time.
// Warps 2x2: warp = 32m x 64n. Fragment-major SMEM staging:
//   A subtile (16m x 8k): 32 lanes x {a0,a1,a2,a3} quad (lds.128)
//   W subtile (8n x 8k):  32 lanes x {b0,b1} pair (lds.64)
__global__ void __launch_bounds__(128, 3)
mm3t(const float* __restrict__ A, int lda,
     const float* __restrict__ W, int ldw,
     float* __restrict__ Y, int ldy, int Ktot)
{
    __shared__ __align__(16) u32 sAh[64*32], sAl[64*32];
    __shared__ __align__(16) u32 sWh[128*32], sWl[128*32];   // 48 KB total
    const int t = threadIdx.x;
    const int w = t >> 5, lane = t & 31;
    const int mw = w >> 1;        // 0..1: 32-row group
    const int nw = w & 1;         // 0..1: 64-col group
    const size_t mBase = (size_t)blockIdx.x * 64;
    const int n0 = blockIdx.y * 128;
    const float* Wp = W + (size_t)n0 * ldw;

    float acc[2][8][4];
    #pragma unroll
    for (int mb = 0; mb < 2; mb++)
        #pragma unroll
        for (int nb = 0; nb < 8; nb++)
            #pragma unroll
            for (int i = 0; i < 4; i++) acc[mb][nb][i] = 0.f;

    const int nch = Ktot >> 5;
    for (int ch = 0; ch < nch; ch++){
        const int k0 = ch << 5;
        // ---- stage A [64 x 32] -> fragment-major hi/lo ----
        #pragma unroll
        for (int q4 = 0; q4 < 4; q4++){
            int q = t + q4*128;
            int row = q >> 3, c4 = (q & 7) << 2;
            float4 v = *(const float4*)(A + (mBase + row)*(size_t)lda + k0 + c4);
            u32 hx = tf32hi(v.x), hy = tf32hi(v.y), hz = tf32hi(v.z), hw = tf32hi(v.w);
            int s = (row >> 4)*4 + (c4 >> 3);
            int base = s*128 + (row & 7)*16 + (((c4 >> 2) & 1) << 1) + ((row >> 3) & 1);
            sAh[base+0] = hx; sAh[base+4] = hy; sAh[base+8] = hz; sAh[base+12] = hw;
            sAl[base+0] = tf32lo(v.x, hx); sAl[base+4]  = tf32lo(v.y, hy);
            sAl[base+8] = tf32lo(v.z, hz); sAl[base+12] = tf32lo(v.w, hw);
        }
        // ---- stage W [128 x 32] -> fragment-major hi/lo ----
        #pragma unroll
        for (int q4 = 0; q4 < 8; q4++){
            int q = t + q4*128;
            int row = q >> 3, c4 = (q & 7) << 2;
            float4 v = *(const float4*)(Wp + (size_t)row*ldw + k0 + c4);
            u32 hx = tf32hi(v.x), hy = tf32hi(v.y), hz = tf32hi(v.z), hw = tf32hi(v.w);
            int s = (row >> 3)*4 + (c4 >> 3);
            int base = s*64 + (row & 7)*8 + ((c4 >> 2) & 1);
            sWh[base+0] = hx; sWh[base+2] = hy; sWh[base+4] = hz; sWh[base+6] = hw;
            sWl[base+0] = tf32lo(v.x, hx); sWl[base+2] = tf32lo(v.y, hy);
            sWl[base+4] = tf32lo(v.z, hz); sWl[base+6] = tf32lo(v.w, hw);
        }
        __syncthreads();

        #pragma unroll
        for (int kb = 0; kb < 4; kb++){
            u32 ah[2][4], al[2][4], bh[8][2], bl[8][2];
            #pragma unroll
            for (int mb = 0; mb < 2; mb++){
                int idx = ((mw*2 + mb)*4 + kb)*128 + lane*4;
                *(uint4*)ah[mb] = *(const uint4*)&sAh[idx];
                *(uint4*)al[mb] = *(const uint4*)&sAl[idx];
            }
            #pragma unroll
            for (int nb = 0; nb < 8; nb++){
                int idx = ((nw*8 + nb)*4 + kb)*64 + lane*2;
                *(uint2*)bh[nb] = *(const uint2*)&sWh[idx];
                *(uint2*)bl[nb] = *(const uint2*)&sWl[idx];
            }
            #pragma unroll
            for (int mb = 0; mb < 2; mb++)
                #pragma unroll
                for (int nb = 0; nb < 8; nb++){
                    mma8(acc[mb][nb], ah[mb], bh[nb]);   // hi*hi
                    mma8(acc[mb][nb], ah[mb], bl[nb]);   // hi*lo
                    mma8(acc[mb][nb], al[mb], bh[nb]);   // lo*hi
                }
        }
        __syncthreads();
    }

    // ---- epilogue: C fragment c0/c1 -> (row g, cols 2t..2t+1), c2/c3 -> row g+8 ----
    const int r = lane >> 2, cp = (lane & 3) << 1;
    #pragma unroll
    for (int mb = 0; mb < 2; mb++){
        const size_t m0 = mBase + mw*32 + mb*16;
        #pragma unroll
        for (int nb = 0; nb < 8; nb++){
            const int col = n0 + nw*64 + nb*8 + cp;
            *(float2*)(Y + (m0 + r)*(size_t)ldy + col)     = make_float2(acc[mb][nb][0], acc[mb][nb][1]);
            *(float2*)(Y + (m0 + r + 8)*(size_t)ldy + col) = make_float2(acc[mb][nb][2], acc[mb][nb][3]);
        }
    }
}

// ---------------- elementwise kernels ----------------
// pos [n][128][3] -> posT [n][3][128]
__global__ void k_tr(const float* __restrict__ in, float* __restrict__ out){
    __shared__ float s[384];
    const size_t n = blockIdx.x;
    const int t = threadIdx.x;
    const float* ip = in + n*384;
    float* op = out + n*384;
    for (int i = t; i < 384; i += 128) s[i] = ip[i];
    __syncthreads();
    for (int i = t; i < 384; i += 128){
        int comp = i >> 7, c = i & 127;
        op[i] = s[c*3 + comp];
    }
}

// VN leaky-relu combine: Y from P, D (layout [3n+i][C]); optional per-seg bias
template<int C>
__global__ void k_lrelu(const float* __restrict__ P, const float* __restrict__ D,
                        const float* __restrict__ Bf, const float* __restrict__ Bd,
                        float* __restrict__ Y, int segLen)
{
    const size_t idx = (size_t)blockIdx.x*256 + threadIdx.x;   // over N*C
    const size_t n = idx / C;
    const int o = (int)(idx - n*C);
    const size_t b = n*(size_t)(3*C) + o;
    float p[3], d[3], ov[3];
    p[0] = P[b]; p[1] = P[b + C]; p[2] = P[b + 2*C];
    d[0] = D[b]; d[1] = D[b + C]; d[2] = D[b + 2*C];
    if (Bf){
        const int s = (int)(n / segLen);
        const float* bf = Bf + ((size_t)s*C + o)*3;
        const float* bd = Bd + ((size_t)s*C + o)*3;
        p[0] += bf[0]; p[1] += bf[1]; p[2] += bf[2];
        d[0] += bd[0]; d[1] += bd[1]; d[2] += bd[2];
    }
    lrelu3(p, d, ov);
    Y[b] = ov[0]; Y[b + C] = ov[1]; Y[b + 2*C] = ov[2];
}

// dot[n][o] = sum_i X[(3n+i)C+o] * D[(3n+i)C+o]
template<int C>
__global__ void k_dot(const float* __restrict__ X, const float* __restrict__ D,
                      float* __restrict__ dv)
{
    const size_t idx = (size_t)blockIdx.x*256 + threadIdx.x;
    const size_t n = idx / C;
    const int o = (int)(idx - n*C);
    const size_t b = n*(size_t)(3*C) + o;
    dv[idx] = fmaf(X[b], D[b], fmaf(X[b + C], D[b + C], X[b + 2*C]*D[b + 2*C]));
}

// segment argmax + gather; V layout [n][3][C]
template<int C>
__global__ void k_segmax(const float* __restrict__ dotv, const float* __restrict__ V,
                         float* __restrict__ pooled, int segLen)
{
    __shared__ float sv[8][32];
    __shared__ int   si[8][32];
    const int ci = threadIdx.x & 31, ri = threadIdx.x >> 5;
    const int c = blockIdx.y * 32 + ci;
    const int s = blockIdx.x;
    const size_t base = (size_t)s * segLen;
    const int per = segLen >> 3;
    const int r0 = ri * per;
    float best = -3.402823466e38f; int bi = 0;
    const float* dp = dotv + (base + r0)*(size_t)C + c;
    for (int r = 0; r < per; r++){
        float v = dp[(size_t)r * C];
        if (v > best){ best = v; bi = r0 + r; }   // strict > keeps smallest index
    }
    sv[ri][ci] = best; si[ri][ci] = bi;
    __syncthreads();
    if (ri == 0){
        #pragma unroll
        for (int k = 1; k < 8; k++){
            float v = sv[k][ci];
            if (v > best){ best = v; bi = si[k][ci]; }
        }
        const size_t row = base + bi;
        const float* xp = V + row*(size_t)(3*C) + c;
        float* op = pooled + ((size_t)s*C + c)*3;
        op[0] = xp[0]; op[1] = xp[C]; op[2] = xp[2*C];
    }
}

// small VNLeakyReLU over [32, C, 3]
template<int C>
__global__ void k_relu_small(const float* __restrict__ Xin, const float* __restrict__ Wr,
                             float* __restrict__ out)
{
    __shared__ float xs[C*3];
    const int s = blockIdx.x, c = threadIdx.x;
    for (int idx = c; idx < C*3; idx += C) xs[idx] = Xin[(size_t)s*C*3 + idx];
    __syncthreads();
    float d0 = 0.f, d1 = 0.f, d2 = 0.f;
    const float* wr = Wr + (size_t)c * C;
    for (int k = 0; k < C; k++){
        float w = wr[k];
        d0 = fmaf(w, xs[k*3 + 0], d0);
        d1 = fmaf(w, xs[k*3 + 1], d1);
        d2 = fmaf(w, xs[k*3 + 2], d2);
    }
    float x0 = xs[c*3], x1 = xs[c*3 + 1], x2 = xs[c*3 + 2];
    float dot = x0*d0 + x1*d1 + x2*d2;
    float dn  = d0*d0 + d1*d1 + d2*d2;
    float f = (dot >= 0.f) ? 0.f : dot * __fdividef(1.f, dn + EPSV);
    float* op = out + ((size_t)s*C + c)*3;
    op[0] = fmaf(-f, d0, x0);
    op[1] = fmaf(-f, d1, x1);
    op[2] = fmaf(-f, d2, x2);
}

// per-segment bias: W4*[:,128:256] @ r3[s]
__global__ void k_bias(const float* __restrict__ r3, const float* __restrict__ W4f,
                       const float* __restrict__ W4d,
                       float* __restrict__ bf, float* __restrict__ bd)
{
    __shared__ float xs[128*3];
    const int s = blockIdx.x, o = threadIdx.x;   // 256 threads
    for (int idx = o; idx < 384; idx += 256) xs[idx] = r3[(size_t)s*384 + idx];
    __syncthreads();
    float f0=0.f,f1=0.f,f2=0.f,e0=0.f,e1=0.f,e2=0.f;
    const float* wf = W4f + (size_t)o*256 + 128;
    const float* wd = W4d + (size_t)o*256 + 128;
    for (int h = 0; h < 128; h++){
        float a = wf[h], b = wd[h];
        f0 = fmaf(a, xs[h*3+0], f0); f1 = fmaf(a, xs[h*3+1], f1); f2 = fmaf(a, xs[h*3+2], f2);
        e0 = fmaf(b, xs[h*3+0], e0); e1 = fmaf(b, xs[h*3+1], e1); e2 = fmaf(b, xs[h*3+2], e2);
    }
    const size_t base = ((size_t)s*256 + o)*3;
    bf[base] = f0; bf[base+1] = f1; bf[base+2] = f2;
    bd[base] = e0; bd[base+1] = e1; bd[base+2] = e2;
}

// ---------------- launch ----------------
extern "C" void kernel_launch(void* const* d_in, const int* in_sizes, int n_in,
                              void* d_out, int out_size)
{
    const float* pos = (const float*)d_in[0];
    const float* W1f = (const float*)d_in[2];
    const float* W1d = (const float*)d_in[3];
    const float* W2f = (const float*)d_in[4];
    const float* W2d = (const float*)d_in[5];
    const float* W3  = (const float*)d_in[6];
    const float* Wd1 = (const float*)d_in[7];
    const float* Wr3 = (const float*)d_in[8];
    const float* W4f = (const float*)d_in[9];
    const float* W4d = (const float*)d_in[10];
    const float* W5  = (const float*)d_in[11];
    const float* Wd2 = (const float*)d_in[12];
    const float* Wr5 = (const float*)d_in[13];

    const int N = in_sizes[0] / 384;
    const int segLen = N / 32;
    const int gm = (3*N) / 64;
    const size_t u = (size_t)3*N*128;

    float *scr,*posT,*p1,*r3,*p2,*bf,*bd;
    cudaGetSymbolAddress((void**)&scr,  g_scr);
    cudaGetSymbolAddress((void**)&posT, g_posT);
    cudaGetSymbolAddress((void**)&p1,   g_pool1);
    cudaGetSymbolAddress((void**)&r3,   g_r3);
    cudaGetSymbolAddress((void**)&p2,   g_pool2);
    cudaGetSymbolAddress((void**)&bf,   g_bf);
    cudaGetSymbolAddress((void**)&bd,   g_bd);

    // aliased regions (6 units total):
    // stage1: S0=P/Dg1, S1=D, S2=y1, S3=y2, S4=y3, S5=dot1buf
    // stage2: R0=[0,2u) P4 then Y5; R2=[2u,4u) D4 then Dg2; R4=[4u,6u) Y4 then dot2buf
    float* S0 = scr;
    float* S1 = scr + u;
    float* S2 = scr + 2*u;
    float* S3 = scr + 3*u;
    float* S4 = scr + 4*u;
    float* S5 = scr + 5*u;
    float* R0 = scr;
    float* R2 = scr + 2*u;
    float* R4 = scr + 4*u;

    const int ewg1 = (N*128)/256, ewg2 = (N*256)/256;

    // stage 1 (C=128)
    k_tr<<<N, 128>>>(pos, posT);
    mm3t<<<dim3(gm,1), 128>>>(posT, 128, W1f, 128, S0, 128, 128);
    mm3t<<<dim3(gm,1), 128>>>(posT, 128, W1d, 128, S1, 128, 128);
    k_lrelu<128><<<ewg1, 256>>>(S0, S1, nullptr, nullptr, S2, segLen);
    mm3t<<<dim3(gm,1), 128>>>(S2, 128, W2f, 128, S0, 128, 128);
    mm3t<<<dim3(gm,1), 128>>>(S2, 128, W2d, 128, S1, 128, 128);
    k_lrelu<128><<<ewg1, 256>>>(S0, S1, nullptr, nullptr, S3, segLen);
    mm3t<<<dim3(gm,1), 128>>>(S3, 128, W3, 128, S4, 128, 128);
    mm3t<<<dim3(gm,1), 128>>>(S4, 128, Wd1, 128, S0, 128, 128);
    k_dot<128><<<ewg1, 256>>>(S4, S0, S5);
    k_segmax<128><<<dim3(32,4), 256>>>(S5, S4, p1, segLen);
    k_relu_small<128><<<32, 128>>>(p1, Wr3, r3);

    // stage 2 (C=256; concat folded into per-segment bias)
    k_bias<<<32, 256>>>(r3, W4f, W4d, bf, bd);
    mm3t<<<dim3(gm,2), 128>>>(posT, 128, W4f, 256, R0, 256, 128);   // P4 -> R0
    mm3t<<<dim3(gm,2), 128>>>(posT, 128, W4d, 256, R2, 256, 128);   // D4 -> R2
    k_lrelu<256><<<ewg2, 256>>>(R0, R2, bf, bd, R4, segLen);        // Y4 -> R4 (P4,D4 dead)
    mm3t<<<dim3(gm,2), 128>>>(R4, 256, W5, 256, R0, 256, 256);      // Y5 -> R0
    mm3t<<<dim3(gm,2), 128>>>(R0, 256, Wd2, 256, R2, 256, 256);     // Dg2 -> R2 (Y4 dead)
    k_dot<256><<<ewg2, 256>>>(R0, R2, R4);                          // dot2 -> R4
    k_segmax<256><<<dim3(32,8), 256>>>(R4, R0, p2, segLen);
    k_relu_small<256><<<32, 256>>>(p2, Wr5, (float*)d_out);
}

// round 17
// speedup vs baseline: 1.4363x; 1.1471x over previous
// GlobalEmdModelVn — 3xTF32 mma.sync pipeline, rev R15: pre-split weights (fragment-major)
#include <cuda_runtime.h>
#include <cstdint>

#define EPSV 1e-7f
typedef unsigned long long u64;
typedef unsigned int u32;

// ---------------- scratch (static; no allocs) ----------------
#define N_MAX 131072
#define UNIT ((size_t)3*N_MAX*128)    // one [3N x 128] matrix
__device__ __align__(1024) float g_scr[6*UNIT];   // 1.21 GB aliased scratch
__device__ __align__(1024) float g_posT[UNIT];    // pos transposed [n][3][128]
__device__ __align__(1024) u32  g_wh[294912];     // weight tf32-hi fragments
__device__ __align__(1024) u32  g_wl[294912];     // weight tf32-lo fragments
__device__ __align__(256)  float g_pool1[32*128*3];
__device__ __align__(256)  float g_r3[32*128*3];
__device__ __align__(256)  float g_pool2[32*256*3];
__device__ __align__(256)  float g_bf[32*256*3];
__device__ __align__(256)  float g_bd[32*256*3];

// ---------------- helpers ----------------
// tf32 round-to-nearest-ties-away (bitwise equivalent of cvt.rna.tf32.f32)
static __device__ __forceinline__ u32 tf32hi(float x){
    u32 b = __float_as_uint(x);
    return (b + 0x1000u) & 0xFFFFE000u;
}
static __device__ __forceinline__ u32 tf32lo(float x, u32 hi){
    u32 b = __float_as_uint(x - __uint_as_float(hi));
    return (b + 0x1000u) & 0xFFFFE000u;
}
static __device__ __forceinline__ void mma8(float* c, const u32* a, const u32* b){
    asm volatile("mma.sync.aligned.m16n8k8.row.col.f32.tf32.tf32.f32 "
        "{%0,%1,%2,%3}, {%4,%5,%6,%7}, {%8,%9}, {%0,%1,%2,%3};"
        : "+f"(c[0]), "+f"(c[1]), "+f"(c[2]), "+f"(c[3])
        : "r"(a[0]), "r"(a[1]), "r"(a[2]), "r"(a[3]), "r"(b[0]), "r"(b[1]));
}

__device__ __forceinline__ void lrelu3(const float p[3], const float d[3], float o[3]){
    float dot = fmaf(p[0], d[0], fmaf(p[1], d[1], p[2]*d[2]));
    float dn  = fmaf(d[0], d[0], fmaf(d[1], d[1], d[2]*d[2]));
    float f = (dot >= 0.f) ? 0.f : dot * __fdividef(1.f, dn + EPSV);
    o[0] = fmaf(-f, d[0], p[0]);
    o[1] = fmaf(-f, d[1], p[1]);
    o[2] = fmaf(-f, d[2], p[2]);
}

// ---------------- weight pre-split: fp32 [NN][K] -> fragment-major tf32 hi/lo ----------------
// Global fragment layout: [kch][nb8][kbl][lane][j] ; value (lane,j) = W[nb8*8 + (lane>>2)]
// [kch*32 + kbl*8 + (lane&3) + j*4]. This is bit-identical to mm3t's SMEM layout, so the
// per-chunk W stage becomes a contiguous 16KB copy.
struct WSplitDesc {
    const float* src[10];
    int ld[10];
    int nn[10];
    u32 off[10];
    u32 total;
};
__global__ void k_wsplit(WSplitDesc d, u32* __restrict__ outH, u32* __restrict__ outL){
    u32 idx = blockIdx.x*256 + threadIdx.x;
    if (idx >= d.total) return;
    int m = 0;
    #pragma unroll
    for (int i = 1; i < 10; i++) if (idx >= d.off[i]) m = i;
    u32 rel = idx - d.off[m];
    int NN8 = d.nn[m] >> 3;
    int l2 = rel & 63;
    u32 rest = rel >> 6;
    int kbl = (int)(rest & 3);
    u32 rest2 = rest >> 2;
    int kch = (int)(rest2 / (u32)NN8);
    int nb8 = (int)(rest2 - (u32)kch*(u32)NN8);
    int lane = l2 >> 1, j = l2 & 1;
    int n = nb8*8 + (lane >> 2);
    int k = kch*32 + kbl*8 + (lane & 3) + j*4;
    float v = d.src[m][(size_t)n*d.ld[m] + k];
    u32 h = tf32hi(v);
    outH[idx] = h;
    outL[idx] = tf32lo(v, h);
}

// ---------------- 3xTF32 mma.sync GEMM (weights pre-split) ----------------
// Y[m][n0+n] = sum_k A[m][k] * W[n0+n][k]; split-precision 3-pass (hi*hi+hi*lo+lo*hi).
// Block: 128 threads, tile 64(M) x 128(N), K staged 32 at a time. Warps 2x2 (32m x 64n).
__global__ void __launch_bounds__(128, 3)
mm3t(const float* __restrict__ A, int lda,
     const u32* __restrict__ Wh, const u32* __restrict__ Wl, int NN8tot,
     float* __restrict__ Y, int ldy, int Ktot)
{
    __shared__ __align__(16) u32 sAh[64*32], sAl[64*32];
    __shared__ __align__(16) u32 sWh[128*32], sWl[128*32];   // 48 KB total
    const int t = threadIdx.x;
    const int w = t >> 5, lane = t & 31;
    const int mw = w >> 1;
    const int nw = w & 1;
    const size_t mBase = (size_t)blockIdx.x * 64;
    const int n0 = blockIdx.y * 128;
    const int n08 = n0 >> 3;

    float acc[2][8][4];
    #pragma unroll
    for (int mb = 0; mb < 2; mb++)
        #pragma unroll
        for (int nb = 0; nb < 8; nb++)
            #pragma unroll
            for (int i = 0; i < 4; i++) acc[mb][nb][i] = 0.f;

    const int nch = Ktot >> 5;
    for (int ch = 0; ch < nch; ch++){
        const int k0 = ch << 5;
        // ---- stage A [64 x 32] -> fragment-major hi/lo (runtime split) ----
        #pragma unroll
        for (int q4 = 0; q4 < 4; q4++){
            int q = t + q4*128;
            int row = q >> 3, c4 = (q & 7) << 2;
            float4 v = *(const float4*)(A + (mBase + row)*(size_t)lda + k0 + c4);
            u32 hx = tf32hi(v.x), hy = tf32hi(v.y), hz = tf32hi(v.z), hw = tf32hi(v.w);
            int s = (row >> 4)*4 + (c4 >> 3);
            int base = s*128 + (row & 7)*16 + (((c4 >> 2) & 1) << 1) + ((row >> 3) & 1);
            sAh[base+0] = hx; sAh[base+4] = hy; sAh[base+8] = hz; sAh[base+12] = hw;
            sAl[base+0] = tf32lo(v.x, hx); sAl[base+4]  = tf32lo(v.y, hy);
            sAl[base+8] = tf32lo(v.z, hz); sAl[base+12] = tf32lo(v.w, hw);
        }
        // ---- stage W: contiguous 16KB copy from pre-split fragments ----
        {
            const uint4* gh = (const uint4*)(Wh + ((size_t)ch*NN8tot + n08)*256u);
            const uint4* gl = (const uint4*)(Wl + ((size_t)ch*NN8tot + n08)*256u);
            uint4* dh = (uint4*)sWh;
            uint4* dl = (uint4*)sWl;
            #pragma unroll
            for (int i = 0; i < 8; i++){
                dh[t + i*128] = gh[t + i*128];
                dl[t + i*128] = gl[t + i*128];
            }
        }
        __syncthreads();

        #pragma unroll
        for (int kb = 0; kb < 4; kb++){
            u32 ah[2][4], al[2][4], bh[8][2], bl[8][2];
            #pragma unroll
            for (int mb = 0; mb < 2; mb++){
                int idx = ((mw*2 + mb)*4 + kb)*128 + lane*4;
                *(uint4*)ah[mb] = *(const uint4*)&sAh[idx];
                *(uint4*)al[mb] = *(const uint4*)&sAl[idx];
            }
            #pragma unroll
            for (int nb = 0; nb < 8; nb++){
                int idx = ((nw*8 + nb)*4 + kb)*64 + lane*2;
                *(uint2*)bh[nb] = *(const uint2*)&sWh[idx];
                *(uint2*)bl[nb] = *(const uint2*)&sWl[idx];
            }
            #pragma unroll
            for (int mb = 0; mb < 2; mb++)
                #pragma unroll
                for (int nb = 0; nb < 8; nb++){
                    mma8(acc[mb][nb], ah[mb], bh[nb]);   // hi*hi
                    mma8(acc[mb][nb], ah[mb], bl[nb]);   // hi*lo
                    mma8(acc[mb][nb], al[mb], bh[nb]);   // lo*hi
                }
        }
        __syncthreads();
    }

    // ---- epilogue ----
    const int r = lane >> 2, cp = (lane & 3) << 1;
    #pragma unroll
    for (int mb = 0; mb < 2; mb++){
        const size_t m0 = mBase + mw*32 + mb*16;
        #pragma unroll
        for (int nb = 0; nb < 8; nb++){
            const int col = n0 + nw*64 + nb*8 + cp;
            *(float2*)(Y + (m0 + r)*(size_t)ldy + col)     = make_float2(acc[mb][nb][0], acc[mb][nb][1]);
            *(float2*)(Y + (m0 + r + 8)*(size_t)ldy + col) = make_float2(acc[mb][nb][2], acc[mb][nb][3]);
        }
    }
}

// ---------------- elementwise kernels ----------------
// pos [n][128][3] -> posT [n][3][128]
__global__ void k_tr(const float* __restrict__ in, float* __restrict__ out){
    __shared__ float s[384];
    const size_t n = blockIdx.x;
    const int t = threadIdx.x;
    const float* ip = in + n*384;
    float* op = out + n*384;
    for (int i = t; i < 384; i += 128) s[i] = ip[i];
    __syncthreads();
    for (int i = t; i < 384; i += 128){
        int comp = i >> 7, c = i & 127;
        op[i] = s[c*3 + comp];
    }
}

// VN leaky-relu combine: Y from P, D (layout [3n+i][C]); optional per-seg bias
template<int C>
__global__ void k_lrelu(const float* __restrict__ P, const float* __restrict__ D,
                        const float* __restrict__ Bf, const float* __restrict__ Bd,
                        float* __restrict__ Y, int segLen)
{
    const size_t idx = (size_t)blockIdx.x*256 + threadIdx.x;
    const size_t n = idx / C;
    const int o = (int)(idx - n*C);
    const size_t b = n*(size_t)(3*C) + o;
    float p[3], d[3], ov[3];
    p[0] = P[b]; p[1] = P[b + C]; p[2] = P[b + 2*C];
    d[0] = D[b]; d[1] = D[b + C]; d[2] = D[b + 2*C];
    if (Bf){
        const int s = (int)(n / segLen);
        const float* bf = Bf + ((size_t)s*C + o)*3;
        const float* bd = Bd + ((size_t)s*C + o)*3;
        p[0] += bf[0]; p[1] += bf[1]; p[2] += bf[2];
        d[0] += bd[0]; d[1] += bd[1]; d[2] += bd[2];
    }
    lrelu3(p, d, ov);
    Y[b] = ov[0]; Y[b + C] = ov[1]; Y[b + 2*C] = ov[2];
}

// dot[n][o] = sum_i X[(3n+i)C+o] * D[(3n+i)C+o]
template<int C>
__global__ void k_dot(const float* __restrict__ X, const float* __restrict__ D,
                      float* __restrict__ dv)
{
    const size_t idx = (size_t)blockIdx.x*256 + threadIdx.x;
    const size_t n = idx / C;
    const int o = (int)(idx - n*C);
    const size_t b = n*(size_t)(3*C) + o;
    dv[idx] = fmaf(X[b], D[b], fmaf(X[b + C], D[b + C], X[b + 2*C]*D[b + 2*C]));
}

// segment argmax + gather; V layout [n][3][C]
template<int C>
__global__ void k_segmax(const float* __restrict__ dotv, const float* __restrict__ V,
                         float* __restrict__ pooled, int segLen)
{
    __shared__ float sv[8][32];
    __shared__ int   si[8][32];
    const int ci = threadIdx.x & 31, ri = threadIdx.x >> 5;
    const int c = blockIdx.y * 32 + ci;
    const int s = blockIdx.x;
    const size_t base = (size_t)s * segLen;
    const int per = segLen >> 3;
    const int r0 = ri * per;
    float best = -3.402823466e38f; int bi = 0;
    const float* dp = dotv + (base + r0)*(size_t)C + c;
    for (int r = 0; r < per; r++){
        float v = dp[(size_t)r * C];
        if (v > best){ best = v; bi = r0 + r; }   // strict > keeps smallest index
    }
    sv[ri][ci] = best; si[ri][ci] = bi;
    __syncthreads();
    if (ri == 0){
        #pragma unroll
        for (int k = 1; k < 8; k++){
            float v = sv[k][ci];
            if (v > best){ best = v; bi = si[k][ci]; }
        }
        const size_t row = base + bi;
        const float* xp = V + row*(size_t)(3*C) + c;
        float* op = pooled + ((size_t)s*C + c)*3;
        op[0] = xp[0]; op[1] = xp[C]; op[2] = xp[2*C];
    }
}

// small VNLeakyReLU over [32, C, 3]
template<int C>
__global__ void k_relu_small(const float* __restrict__ Xin, const float* __restrict__ Wr,
                             float* __restrict__ out)
{
    __shared__ float xs[C*3];
    const int s = blockIdx.x, c = threadIdx.x;
    for (int idx = c; idx < C*3; idx += C) xs[idx] = Xin[(size_t)s*C*3 + idx];
    __syncthreads();
    float d0 = 0.f, d1 = 0.f, d2 = 0.f;
    const float* wr = Wr + (size_t)c * C;
    for (int k = 0; k < C; k++){
        float w = wr[k];
        d0 = fmaf(w, xs[k*3 + 0], d0);
        d1 = fmaf(w, xs[k*3 + 1], d1);
        d2 = fmaf(w, xs[k*3 + 2], d2);
    }
    float x0 = xs[c*3], x1 = xs[c*3 + 1], x2 = xs[c*3 + 2];
    float dot = x0*d0 + x1*d1 + x2*d2;
    float dn  = d0*d0 + d1*d1 + d2*d2;
    float f = (dot >= 0.f) ? 0.f : dot * __fdividef(1.f, dn + EPSV);
    float* op = out + ((size_t)s*C + c)*3;
    op[0] = fmaf(-f, d0, x0);
    op[1] = fmaf(-f, d1, x1);
    op[2] = fmaf(-f, d2, x2);
}

// per-segment bias: W4*[:,128:256] @ r3[s]
__global__ void k_bias(const float* __restrict__ r3, const float* __restrict__ W4f,
                       const float* __restrict__ W4d,
                       float* __restrict__ bf, float* __restrict__ bd)
{
    __shared__ float xs[128*3];
    const int s = blockIdx.x, o = threadIdx.x;   // 256 threads
    for (int idx = o; idx < 384; idx += 256) xs[idx] = r3[(size_t)s*384 + idx];
    __syncthreads();
    float f0=0.f,f1=0.f,f2=0.f,e0=0.f,e1=0.f,e2=0.f;
    const float* wf = W4f + (size_t)o*256 + 128;
    const float* wd = W4d + (size_t)o*256 + 128;
    for (int h = 0; h < 128; h++){
        float a = wf[h], b = wd[h];
        f0 = fmaf(a, xs[h*3+0], f0); f1 = fmaf(a, xs[h*3+1], f1); f2 = fmaf(a, xs[h*3+2], f2);
        e0 = fmaf(b, xs[h*3+0], e0); e1 = fmaf(b, xs[h*3+1], e1); e2 = fmaf(b, xs[h*3+2], e2);
    }
    const size_t base = ((size_t)s*256 + o)*3;
    bf[base] = f0; bf[base+1] = f1; bf[base+2] = f2;
    bd[base] = e0; bd[base+1] = e1; bd[base+2] = e2;
}

// ---------------- launch ----------------
extern "C" void kernel_launch(void* const* d_in, const int* in_sizes, int n_in,
                              void* d_out, int out_size)
{
    const float* pos = (const float*)d_in[0];
    const float* W1f = (const float*)d_in[2];
    const float* W1d = (const float*)d_in[3];
    const float* W2f = (const float*)d_in[4];
    const float* W2d = (const float*)d_in[5];
    const float* W3  = (const float*)d_in[6];
    const float* Wd1 = (const float*)d_in[7];
    const float* Wr3 = (const float*)d_in[8];
    const float* W4f = (const float*)d_in[9];
    const float* W4d = (const float*)d_in[10];
    const float* W5  = (const float*)d_in[11];
    const float* Wd2 = (const float*)d_in[12];
    const float* Wr5 = (const float*)d_in[13];

    const int N = in_sizes[0] / 384;
    const int segLen = N / 32;
    const int gm = (3*N) / 64;
    const size_t u = (size_t)3*N*128;

    float *scr,*posT,*p1,*r3,*p2,*bf,*bd;
    u32 *wh,*wl;
    cudaGetSymbolAddress((void**)&scr,  g_scr);
    cudaGetSymbolAddress((void**)&posT, g_posT);
    cudaGetSymbolAddress((void**)&wh,   g_wh);
    cudaGetSymbolAddress((void**)&wl,   g_wl);
    cudaGetSymbolAddress((void**)&p1,   g_pool1);
    cudaGetSymbolAddress((void**)&r3,   g_r3);
    cudaGetSymbolAddress((void**)&p2,   g_pool2);
    cudaGetSymbolAddress((void**)&bf,   g_bf);
    cudaGetSymbolAddress((void**)&bd,   g_bd);

    // weight-split offsets (u32 elements)
    const u32 oW1f=0, oW1d=16384, oW2f=32768, oW2d=49152, oW3=65536, oWd1=81920,
              oW4f=98304, oW4d=131072, oW5=163840, oWd2=229376, TOT=294912;

    WSplitDesc wd;
    wd.src[0]=W1f; wd.ld[0]=128; wd.nn[0]=128; wd.off[0]=oW1f;
    wd.src[1]=W1d; wd.ld[1]=128; wd.nn[1]=128; wd.off[1]=oW1d;
    wd.src[2]=W2f; wd.ld[2]=128; wd.nn[2]=128; wd.off[2]=oW2f;
    wd.src[3]=W2d; wd.ld[3]=128; wd.nn[3]=128; wd.off[3]=oW2d;
    wd.src[4]=W3;  wd.ld[4]=128; wd.nn[4]=128; wd.off[4]=oW3;
    wd.src[5]=Wd1; wd.ld[5]=128; wd.nn[5]=128; wd.off[5]=oWd1;
    wd.src[6]=W4f; wd.ld[6]=256; wd.nn[6]=256; wd.off[6]=oW4f;   // K=128 (first half of rows' cols)
    wd.src[7]=W4d; wd.ld[7]=256; wd.nn[7]=256; wd.off[7]=oW4d;
    wd.src[8]=W5;  wd.ld[8]=256; wd.nn[8]=256; wd.off[8]=oW5;    // K=256
    wd.src[9]=Wd2; wd.ld[9]=256; wd.nn[9]=256; wd.off[9]=oWd2;
    wd.total = TOT;

    // aliased scratch regions (6 units):
    float* S0 = scr;
    float* S1 = scr + u;
    float* S2 = scr + 2*u;
    float* S3 = scr + 3*u;
    float* S4 = scr + 4*u;
    float* S5 = scr + 5*u;
    float* R0 = scr;
    float* R2 = scr + 2*u;
    float* R4 = scr + 4*u;

    const int ewg1 = (N*128)/256, ewg2 = (N*256)/256;

    k_wsplit<<<(TOT + 255)/256, 256>>>(wd, wh, wl);
    k_tr<<<N, 128>>>(pos, posT);

    // stage 1 (C=128)
    mm3t<<<dim3(gm,1), 128>>>(posT, 128, wh+oW1f, wl+oW1f, 16, S0, 128, 128);
    mm3t<<<dim3(gm,1), 128>>>(posT, 128, wh+oW1d, wl+oW1d, 16, S1, 128, 128);
    k_lrelu<128><<<ewg1, 256>>>(S0, S1, nullptr, nullptr, S2, segLen);
    mm3t<<<dim3(gm,1), 128>>>(S2, 128, wh+oW2f, wl+oW2f, 16, S0, 128, 128);
    mm3t<<<dim3(gm,1), 128>>>(S2, 128, wh+oW2d, wl+oW2d, 16, S1, 128, 128);
    k_lrelu<128><<<ewg1, 256>>>(S0, S1, nullptr, nullptr, S3, segLen);
    mm3t<<<dim3(gm,1), 128>>>(S3, 128, wh+oW3, wl+oW3, 16, S4, 128, 128);
    mm3t<<<dim3(gm,1), 128>>>(S4, 128, wh+oWd1, wl+oWd1, 16, S0, 128, 128);
    k_dot<128><<<ewg1, 256>>>(S4, S0, S5);
    k_segmax<128><<<dim3(32,4), 256>>>(S5, S4, p1, segLen);
    k_relu_small<128><<<32, 128>>>(p1, Wr3, r3);

    // stage 2 (C=256; concat folded into per-segment bias)
    k_bias<<<32, 256>>>(r3, W4f, W4d, bf, bd);
    mm3t<<<dim3(gm,2), 128>>>(posT, 128, wh+oW4f, wl+oW4f, 32, R0, 256, 128);   // P4 -> R0
    mm3t<<<dim3(gm,2), 128>>>(posT, 128, wh+oW4d, wl+oW4d, 32, R2, 256, 128);   // D4 -> R2
    k_lrelu<256><<<ewg2, 256>>>(R0, R2, bf, bd, R4, segLen);                    // Y4 -> R4
    mm3t<<<dim3(gm,2), 128>>>(R4, 256, wh+oW5, wl+oW5, 32, R0, 256, 256);       // Y5 -> R0
    mm3t<<<dim3(gm,2), 128>>>(R0, 256, wh+oWd2, wl+oWd2, 32, R2, 256, 256);     // Dg2 -> R2
    k_dot<256><<<ewg2, 256>>>(R0, R2, R4);                                      // dot2 -> R4
    k_segmax<256><<<dim3(32,8), 256>>>(R4, R0, p2, segLen);
    k_relu_small<256><<<32, 256>>>(p2, Wr5, (float*)d_out);
}